// round 15
// baseline (speedup 1.0000x reference)
#include <cuda_runtime.h>
#include <cuda_bf16.h>
#include <cuda_fp16.h>
#include <cstdint>

// Problem constants
#define Bq   4
#define Nq   8192
#define DIMq 512
#define HEADSq 8
#define DHq  64
#define INNERq 512
#define QKV_COLS 1536
#define M_TOTAL (Bq * Nq)          // 32768
#define BH (Bq * HEADSq)           // 32
#define SCALEq 0.125f
#define CHUNKS 32
#define REC 65

// ---------------- scratch (device globals; no allocation allowed) ----------
__device__ __align__(128) __half g_qkv[M_TOTAL * QKV_COLS];     // 100 MB fp16
__device__ __align__(128) __half g_xh[M_TOTAL * DIMq];
__device__ __align__(128) __half g_Rh[M_TOTAL * INNERq];
__device__ __align__(128) __half g_Wqh[QKV_COLS * DIMq];
__device__ __align__(128) __half g_Woh[DIMq * INNERq];
__device__ float g_gq[BH * DHq];
__device__ float g_gk[BH * DHq];
__device__ float g_wvec[BH * DHq];
__device__ float g_part[BH * CHUNKS * REC];

// =================== base-ISA helpers (sm_80+: cp.async / ldmatrix / mma) ===
__device__ __forceinline__ uint32_t smem_u32(const void* p) {
    uint32_t a;
    asm("{ .reg .u64 t; cvta.to.shared.u64 t, %1; cvt.u32.u64 %0, t; }"
        : "=r"(a) : "l"(p));
    return a;
}
__device__ __forceinline__ void cp_async16(uint32_t dst, const void* src) {
    asm volatile("cp.async.cg.shared.global [%0], [%1], 16;"
                 :: "r"(dst), "l"(src));
}
__device__ __forceinline__ void cp_commit() {
    asm volatile("cp.async.commit_group;");
}
template <int N>
__device__ __forceinline__ void cp_wait() {
    asm volatile("cp.async.wait_group %0;" :: "n"(N));
}
__device__ __forceinline__ void ldsm_x4(uint32_t addr, uint32_t* r) {
    asm volatile("ldmatrix.sync.aligned.m8n8.x4.shared.b16 {%0,%1,%2,%3}, [%4];"
                 : "=r"(r[0]), "=r"(r[1]), "=r"(r[2]), "=r"(r[3]) : "r"(addr));
}
__device__ __forceinline__ void mma_16816(float* c, const uint32_t* a,
                                          uint32_t b0, uint32_t b1) {
    asm volatile(
        "mma.sync.aligned.m16n8k16.row.col.f32.f16.f16.f32 "
        "{%0,%1,%2,%3}, {%4,%5,%6,%7}, {%8,%9}, {%0,%1,%2,%3};"
        : "+f"(c[0]), "+f"(c[1]), "+f"(c[2]), "+f"(c[3])
        : "r"(a[0]), "r"(a[1]), "r"(a[2]), "r"(a[3]), "r"(b0), "r"(b1));
}

// =================== fp32 -> fp16 convert ===================================
__global__ __launch_bounds__(256)
void convert_h_kernel(const float* __restrict__ in, __half* __restrict__ hi) {
    size_t i = ((size_t)blockIdx.x * 256 + threadIdx.x) * 4;
    float4 v = *reinterpret_cast<const float4*>(in + i);
    __half2 h0 = __float22half2_rn(make_float2(v.x, v.y));
    __half2 h1 = __float22half2_rn(make_float2(v.z, v.w));
    *reinterpret_cast<uint2*>(hi + i) = make_uint2(
        *reinterpret_cast<uint32_t*>(&h0), *reinterpret_cast<uint32_t*>(&h1));
}

// =================== HMMA fp16 x1 GEMM (base ISA) ===========================
// C[M,Ntot] = fp16(A)[M,512] @ fp16(B)[Ntot,512]^T (+bias), fp32 accum.
// Block 128x256, BK=32, 8 warps (2x4 grid of 64x64 warp tiles), 256 threads;
// rows padded to 80B; 3-stage cp.async; 1 CTA/SM. Halves A-from-L2 traffic
// vs BN=128 (6 column tiles instead of 12).
#define A_TILE_B 10240              // 128 rows * 80 bytes
#define B_TILE_B 20480              // 256 rows * 80 bytes
#define NSTAGE   3
#define STAGE_TOT (A_TILE_B + B_TILE_B)    // 30720
#define GSMEM_BYTES (NSTAGE * STAGE_TOT)   // 92160 B

template <bool BIAS, typename OT>
__global__ __launch_bounds__(256, 1)
void gemm_mma_x1(const __half* __restrict__ Ah, const __half* __restrict__ Bh,
                 const float* __restrict__ bias, OT* __restrict__ C, int Ntot) {
    extern __shared__ __align__(128) char smem[];
    const uint32_t sb = smem_u32(smem);
    const int tid = threadIdx.x;
    const int wid = tid >> 5, lane = tid & 31;
    const int wm = wid & 1;          // 2 warps along M (64 rows each)
    const int wn = wid >> 1;         // 4 warps along N (64 cols each)
    const int bm = blockIdx.y * 128;
    const int bn = blockIdx.x * 256;

    const __half* srcA = Ah + (size_t)bm * 512;
    const __half* srcB = Bh + (size_t)bn * 512;

    // Per stage: A = 512 chunks of 16B, B = 1024 chunks. 6 chunks/thread.
#define ISSUE_STAGE(BUF, K0)                                                   \
    {                                                                          \
        uint32_t baseA = sb + (BUF) * STAGE_TOT;                               \
        uint32_t baseB = baseA + A_TILE_B;                                     \
        _Pragma("unroll")                                                      \
        for (int i = 0; i < 2; i++) {                                          \
            int ch = i * 256 + tid;                                            \
            int r = ch >> 2, c = ch & 3;                                       \
            cp_async16(baseA + r * 80 + c * 16,                                \
                       srcA + (size_t)r * 512 + (K0) + c * 8);                 \
        }                                                                      \
        _Pragma("unroll")                                                      \
        for (int i = 0; i < 4; i++) {                                          \
            int ch = i * 256 + tid;                                            \
            int r = ch >> 2, c = ch & 3;                                       \
            cp_async16(baseB + r * 80 + c * 16,                                \
                       srcB + (size_t)r * 512 + (K0) + c * 8);                 \
        }                                                                      \
        cp_commit();                                                           \
    }

    float acc[4][8][4];
#pragma unroll
    for (int i = 0; i < 4; i++)
#pragma unroll
        for (int j = 0; j < 8; j++)
#pragma unroll
            for (int k = 0; k < 4; k++) acc[i][j][k] = 0.f;

    ISSUE_STAGE(0, 0)
    ISSUE_STAGE(1, 32)

    const uint32_t a_row = (lane & 15);
    const uint32_t a_half = (lane >> 4) * 16;
    const uint32_t b_row = (lane & 7) + ((lane >> 4) & 1) * 8;
    const uint32_t b_half = ((lane >> 3) & 1) * 16;

#pragma unroll 1
    for (int kb = 0; kb < 16; kb++) {
        if (kb < 14) ISSUE_STAGE((kb + 2) % NSTAGE, (kb + 2) * 32);
        if (kb < 14) cp_wait<2>();
        else if (kb == 14) cp_wait<1>();
        else cp_wait<0>();
        __syncthreads();

        const uint32_t sA = sb + (kb % NSTAGE) * STAGE_TOT;
        const uint32_t sB = sA + A_TILE_B;
#pragma unroll
        for (int ks = 0; ks < 2; ks++) {
            uint32_t aH[4][4], bH[4][4];
#pragma unroll
            for (int mt = 0; mt < 4; mt++) {
                uint32_t arow = (wm * 64 + mt * 16 + a_row) * 80 + a_half + ks * 32;
                ldsm_x4(sA + arow, aH[mt]);
            }
#pragma unroll
            for (int nt2 = 0; nt2 < 4; nt2++) {
                uint32_t brow = (wn * 64 + nt2 * 16 + b_row) * 80 + b_half + ks * 32;
                ldsm_x4(sB + brow, bH[nt2]);
            }
#pragma unroll
            for (int mt = 0; mt < 4; mt++)
#pragma unroll
                for (int nt2 = 0; nt2 < 4; nt2++) {
                    mma_16816(acc[mt][nt2 * 2 + 0], aH[mt], bH[nt2][0], bH[nt2][1]);
                    mma_16816(acc[mt][nt2 * 2 + 1], aH[mt], bH[nt2][2], bH[nt2][3]);
                }
        }
        __syncthreads();
    }
#undef ISSUE_STAGE

#pragma unroll
    for (int mt = 0; mt < 4; mt++) {
        int row = bm + wm * 64 + mt * 16 + (lane >> 2);
#pragma unroll
        for (int nt = 0; nt < 8; nt++) {
            int col = bn + wn * 64 + nt * 8 + 2 * (lane & 3);
            float bx = 0.f, by = 0.f;
            if (BIAS) { bx = __ldg(bias + col); by = __ldg(bias + col + 1); }
            float v00 = acc[mt][nt][0] + bx, v01 = acc[mt][nt][1] + by;
            float v10 = acc[mt][nt][2] + bx, v11 = acc[mt][nt][3] + by;
            if constexpr (sizeof(OT) == 2) {
                *reinterpret_cast<__half2*>((__half*)C + (size_t)row * Ntot + col) =
                    __floats2half2_rn(v00, v01);
                *reinterpret_cast<__half2*>((__half*)C + (size_t)(row + 8) * Ntot + col) =
                    __floats2half2_rn(v10, v11);
            } else {
                *reinterpret_cast<float2*>((float*)C + (size_t)row * Ntot + col) =
                    make_float2(v00, v01);
                *reinterpret_cast<float2*>((float*)C + (size_t)(row + 8) * Ntot + col) =
                    make_float2(v10, v11);
            }
        }
    }
}

// =================== weight-vector prep =====================================
__global__ void make_wq(const float* __restrict__ wql, float* __restrict__ wvec) {
    int t = blockIdx.x * blockDim.x + threadIdx.x;
    if (t < BH * DHq) wvec[t] = wql[t & 63];
}
__global__ void make_wk(const float* __restrict__ wkl, const float* __restrict__ gq,
                        float* __restrict__ wvec) {
    int t = blockIdx.x * blockDim.x + threadIdx.x;
    if (t < BH * DHq) wvec[t] = wkl[t & 63] * gq[t];
}

// ============ fused softmax partial: logits + exp + weighted sums ===========
#define FPAD 72   // halfs per token in smem (144 B, 16B-aligned)

__global__ __launch_bounds__(256)
void fused_softmax_partial(const __half* __restrict__ qkv, int off,
                           const float* __restrict__ wvec,
                           const unsigned char* __restrict__ mask,
                           float* __restrict__ part) {
    __shared__ __align__(16) __half sq[256 * FPAD];
    __shared__ float swv[64];
    __shared__ float sw[256];
    __shared__ float red[256];
    __shared__ float sv[4][64];

    const int chunk = blockIdx.x, bh = blockIdx.y;
    const int b = bh >> 3, h = bh & 7;
    const int tid = threadIdx.x;
    const int row0 = b * Nq + h * 1024 + chunk * 32;

#pragma unroll
    for (int i = 0; i < 8; i++) {
        int ch = i * 256 + tid;
        int tl = ch >> 3, d8 = ch & 7;
        const __half* src = qkv + (size_t)(row0 + (tl >> 3)) * QKV_COLS
                            + off + (tl & 7) * 64 + d8 * 8;
        *reinterpret_cast<uint4*>(sq + tl * FPAD + d8 * 8) =
            *reinterpret_cast<const uint4*>(src);
    }
    if (tid < 64) swv[tid] = wvec[bh * 64 + tid];
    __syncthreads();

    float dot = 0.f;
    const __half* q = sq + tid * FPAD;
#pragma unroll
    for (int d = 0; d < 64; d += 2) {
        float2 qq = __half22float2(*reinterpret_cast<const __half2*>(q + d));
        dot += qq.x * swv[d] + qq.y * swv[d + 1];
    }
    float w = __expf(dot * SCALEq);
    if (mask[b * Nq + chunk * 256 + tid]) w = 0.f;
    sw[tid] = w;
    red[tid] = w;
    __syncthreads();
    for (int s = 128; s > 0; s >>= 1) {
        if (tid < s) red[tid] += red[tid + s];
        __syncthreads();
    }

    const int d = tid & 63, g = tid >> 6;
    float acc = 0.f;
#pragma unroll 8
    for (int tl = g * 64; tl < g * 64 + 64; tl++)
        acc += sw[tl] * __half2float(sq[tl * FPAD + d]);
    sv[g][d] = acc;
    __syncthreads();
    if (tid < 64) {
        float* rec = part + (size_t)(bh * CHUNKS + chunk) * REC;
        rec[tid] = sv[0][tid] + sv[1][tid] + sv[2][tid] + sv[3][tid];
        if (tid == 0) rec[64] = red[0];
    }
}

__global__ void finalize_reduce(const float* __restrict__ part,
                                float* __restrict__ gout) {
    int bh = blockIdx.x;
    int d = threadIdx.x;
    const float* base = part + (size_t)bh * CHUNKS * REC;
    float v = 0.f, w = 0.f;
#pragma unroll
    for (int c = 0; c < CHUNKS; c++) {
        v += base[c * REC + d];
        w += base[c * REC + 64];
    }
    gout[bh * 64 + d] = v / w;
}

// ============ compute_r via HMMA: R = A'[256x64] @ Mw^T + q + b_r ===========
#define CR_ROWS 32
#define CR_PAD  72

__global__ __launch_bounds__(256)
void compute_r_mma(const __half* __restrict__ qkv,
                   const float* __restrict__ gk,
                   const float* __restrict__ W_r,
                   const float* __restrict__ b_r,
                   __half* __restrict__ Rh) {
    __shared__ __align__(16) __half sA[256 * CR_PAD];
    __shared__ __align__(16) __half sB[64 * CR_PAD];
    __shared__ float sbr[64];

    const int tid = threadIdx.x;
    const int wid = tid >> 5, lane = tid & 31;
    const int row0 = blockIdx.x * CR_ROWS;
    const int bh = (row0 >> 13) * 8 + ((row0 & (Nq - 1)) >> 10);

#pragma unroll
    for (int i = 0; i < 8; i++) {
        int ch = i * 256 + tid;
        int tok = ch >> 3, d8 = ch & 7;
        const __half* src = qkv + (size_t)(row0 + (tok >> 3)) * QKV_COLS
                            + 1024 + (tok & 7) * 64 + d8 * 8;
        *reinterpret_cast<uint4*>(sA + tok * CR_PAD + d8 * 8) =
            *reinterpret_cast<const uint4*>(src);
    }

    {
        int e = tid >> 2, db = (tid & 3) * 16;
        const float* wr = W_r + e * 64 + db;
        const float* gkp = gk + bh * 64 + db;
        __half tmp[16];
#pragma unroll
        for (int j = 0; j < 16; j += 4) {
            float4 w4 = *reinterpret_cast<const float4*>(wr + j);
            float4 g4 = *reinterpret_cast<const float4*>(gkp + j);
            tmp[j + 0] = __float2half_rn(w4.x * g4.x);
            tmp[j + 1] = __float2half_rn(w4.y * g4.y);
            tmp[j + 2] = __float2half_rn(w4.z * g4.z);
            tmp[j + 3] = __float2half_rn(w4.w * g4.w);
        }
        *reinterpret_cast<uint4*>(sB + e * CR_PAD + db) =
            *reinterpret_cast<uint4*>(tmp);
        *reinterpret_cast<uint4*>(sB + e * CR_PAD + db + 8) =
            *reinterpret_cast<uint4*>(tmp + 8);
    }
    if (tid < 64) sbr[tid] = b_r[tid];
    __syncthreads();

    const uint32_t sAu = smem_u32(sA);
    const uint32_t sBu = smem_u32(sB);
    const uint32_t a_row = (lane & 15);
    const uint32_t a_half = (lane >> 4) * 16;
    const uint32_t b_row = (lane & 7) + ((lane >> 4) & 1) * 8;
    const uint32_t b_half = ((lane >> 3) & 1) * 16;

    float c[2][8][4];
#pragma unroll
    for (int i = 0; i < 2; i++)
#pragma unroll
        for (int j = 0; j < 8; j++)
#pragma unroll
            for (int k = 0; k < 4; k++) c[i][j][k] = 0.f;

#pragma unroll
    for (int k = 0; k < 4; k++) {
        uint32_t aH[2][4], bH[4][4];
#pragma unroll
        for (int mt = 0; mt < 2; mt++)
            ldsm_x4(sAu + (wid * 32 + mt * 16 + a_row) * 144 + a_half + k * 32,
                    aH[mt]);
#pragma unroll
        for (int nt2 = 0; nt2 < 4; nt2++)
            ldsm_x4(sBu + (nt2 * 16 + b_row) * 144 + b_half + k * 32, bH[nt2]);
#pragma unroll
        for (int mt = 0; mt < 2; mt++)
#pragma unroll
            for (int nt2 = 0; nt2 < 4; nt2++) {
                mma_16816(c[mt][nt2 * 2 + 0], aH[mt], bH[nt2][0], bH[nt2][1]);
                mma_16816(c[mt][nt2 * 2 + 1], aH[mt], bH[nt2][2], bH[nt2][3]);
            }
    }

#pragma unroll
    for (int mt = 0; mt < 2; mt++) {
        int t0 = wid * 32 + mt * 16 + (lane >> 2);
#pragma unroll
        for (int nt = 0; nt < 8; nt++) {
            int e = nt * 8 + 2 * (lane & 3);
            float br0 = sbr[e], br1 = sbr[e + 1];
#pragma unroll
            for (int half = 0; half < 2; half++) {
                int t = t0 + half * 8;
                size_t base = (size_t)(row0 + (t >> 3));
                int col = (t & 7) * 64 + e;
                float2 q = __half22float2(*reinterpret_cast<const __half2*>(
                    qkv + base * QKV_COLS + col));
                float o0 = c[mt][nt][half * 2 + 0] + q.x + br0;
                float o1 = c[mt][nt][half * 2 + 1] + q.y + br1;
                __half2 hv = __floats2half2_rn(o0, o1);
                *reinterpret_cast<__half2*>(Rh + base * INNERq + col) = hv;
            }
        }
    }
}

// ---------------- launcher --------------------------------------------------
extern "C" void kernel_launch(void* const* d_in, const int* in_sizes, int n_in,
                              void* d_out, int out_size) {
    const float* x     = (const float*)d_in[0];
    const unsigned char* mask = (const unsigned char*)d_in[1];
    const float* W_qkv = (const float*)d_in[2];
    const float* w_q   = (const float*)d_in[3];
    const float* w_k   = (const float*)d_in[4];
    const float* W_r   = (const float*)d_in[5];
    const float* b_r   = (const float*)d_in[6];
    const float* W_out = (const float*)d_in[7];
    const float* b_out = (const float*)d_in[8];
    float* out = (float*)d_out;

    float *gq, *gk, *wvec, *part;
    __half *qkv, *xh, *Rh, *Wqh, *Woh;
    cudaGetSymbolAddress((void**)&qkv,  g_qkv);
    cudaGetSymbolAddress((void**)&gq,   g_gq);
    cudaGetSymbolAddress((void**)&gk,   g_gk);
    cudaGetSymbolAddress((void**)&wvec, g_wvec);
    cudaGetSymbolAddress((void**)&part, g_part);
    cudaGetSymbolAddress((void**)&xh,   g_xh);
    cudaGetSymbolAddress((void**)&Rh,   g_Rh);
    cudaGetSymbolAddress((void**)&Wqh,  g_Wqh);
    cudaGetSymbolAddress((void**)&Woh,  g_Woh);

    static int smem_set = 0;
    if (!smem_set) {
        cudaFuncSetAttribute((const void*)gemm_mma_x1<false, __half>,
                             cudaFuncAttributeMaxDynamicSharedMemorySize, GSMEM_BYTES);
        cudaFuncSetAttribute((const void*)gemm_mma_x1<true, float>,
                             cudaFuncAttributeMaxDynamicSharedMemorySize, GSMEM_BYTES);
        smem_set = 1;
    }

    // 0) conversions: x -> fp16; weights -> fp16
    convert_h_kernel<<<(M_TOTAL * DIMq) / 1024, 256>>>(x, xh);
    convert_h_kernel<<<(QKV_COLS * DIMq) / 1024, 256>>>(W_qkv, Wqh);
    convert_h_kernel<<<(DIMq * INNERq) / 1024, 256>>>(W_out, Woh);

    // 1) qkv = x @ W_qkv^T  (HMMA fp16 x1, 128x256 tiles, fp16 output)
    gemm_mma_x1<false, __half><<<dim3(QKV_COLS / 256, M_TOTAL / 128), 256,
                                 GSMEM_BYTES>>>(xh, Wqh, nullptr, qkv, QKV_COLS);

    // 2) q softmax -> global_q  (fused logits+exp+partial)
    make_wq<<<(BH * DHq + 255) / 256, 256>>>(w_q, wvec);
    fused_softmax_partial<<<dim3(CHUNKS, BH), 256>>>(qkv, 0, wvec, mask, part);
    finalize_reduce<<<BH, 64>>>(part, gq);

    // 3) k softmax -> global_k
    make_wk<<<(BH * DHq + 255) / 256, 256>>>(w_k, gq, wvec);
    fused_softmax_partial<<<dim3(CHUNKS, BH), 256>>>(qkv, DIMq, wvec, mask, part);
    finalize_reduce<<<BH, 64>>>(part, gk);

    // 4) r = (v*gk) @ W_r^T + b_r + q  (HMMA, fp16 in/out)
    compute_r_mma<<<M_TOTAL / CR_ROWS, 256>>>(qkv, gk, W_r, b_r, Rh);

    // 5) out = r @ W_out^T + b_out  (HMMA fp16 x1, 128x256 tiles, fp32 output)
    gemm_mma_x1<true, float><<<dim3(INNERq / 256, M_TOTAL / 128), 256,
                               GSMEM_BYTES>>>(Rh, Woh, b_out, out, INNERq);
}

// round 16
// speedup vs baseline: 1.3929x; 1.3929x over previous
#include <cuda_runtime.h>
#include <cuda_bf16.h>
#include <cuda_fp16.h>
#include <cstdint>

// Problem constants
#define Bq   4
#define Nq   8192
#define DIMq 512
#define HEADSq 8
#define DHq  64
#define INNERq 512
#define QKV_COLS 1536
#define M_TOTAL (Bq * Nq)          // 32768
#define BH (Bq * HEADSq)           // 32
#define SCALEq 0.125f
#define CHUNKS 32
#define REC 65

// ---------------- scratch (device globals; no allocation allowed) ----------
__device__ __align__(128) __half g_qkv[M_TOTAL * QKV_COLS];     // 100 MB fp16
__device__ __align__(128) __half g_xh[M_TOTAL * DIMq];
__device__ __align__(128) __half g_Rh[M_TOTAL * INNERq];
__device__ __align__(128) __half g_Wqh[QKV_COLS * DIMq];
__device__ __align__(128) __half g_Woh[DIMq * INNERq];
__device__ float g_gq[BH * DHq];
__device__ float g_gk[BH * DHq];
__device__ float g_wvec[BH * DHq];
__device__ float g_part[BH * CHUNKS * REC];

// =================== base-ISA helpers (sm_80+: cp.async / ldmatrix / mma) ===
__device__ __forceinline__ uint32_t smem_u32(const void* p) {
    uint32_t a;
    asm("{ .reg .u64 t; cvta.to.shared.u64 t, %1; cvt.u32.u64 %0, t; }"
        : "=r"(a) : "l"(p));
    return a;
}
__device__ __forceinline__ void cp_async16(uint32_t dst, const void* src) {
    asm volatile("cp.async.cg.shared.global [%0], [%1], 16;"
                 :: "r"(dst), "l"(src));
}
__device__ __forceinline__ void cp_commit() {
    asm volatile("cp.async.commit_group;");
}
template <int N>
__device__ __forceinline__ void cp_wait() {
    asm volatile("cp.async.wait_group %0;" :: "n"(N));
}
__device__ __forceinline__ void ldsm_x4(uint32_t addr, uint32_t* r) {
    asm volatile("ldmatrix.sync.aligned.m8n8.x4.shared.b16 {%0,%1,%2,%3}, [%4];"
                 : "=r"(r[0]), "=r"(r[1]), "=r"(r[2]), "=r"(r[3]) : "r"(addr));
}
__device__ __forceinline__ void mma_16816(float* c, const uint32_t* a,
                                          uint32_t b0, uint32_t b1) {
    asm volatile(
        "mma.sync.aligned.m16n8k16.row.col.f32.f16.f16.f32 "
        "{%0,%1,%2,%3}, {%4,%5,%6,%7}, {%8,%9}, {%0,%1,%2,%3};"
        : "+f"(c[0]), "+f"(c[1]), "+f"(c[2]), "+f"(c[3])
        : "r"(a[0]), "r"(a[1]), "r"(a[2]), "r"(a[3]), "r"(b0), "r"(b1));
}

// =================== fp32 -> fp16 convert ===================================
__global__ __launch_bounds__(256)
void convert_h_kernel(const float* __restrict__ in, __half* __restrict__ hi) {
    size_t i = ((size_t)blockIdx.x * 256 + threadIdx.x) * 4;
    float4 v = *reinterpret_cast<const float4*>(in + i);
    __half2 h0 = __float22half2_rn(make_float2(v.x, v.y));
    __half2 h1 = __float22half2_rn(make_float2(v.z, v.w));
    *reinterpret_cast<uint2*>(hi + i) = make_uint2(
        *reinterpret_cast<uint32_t*>(&h0), *reinterpret_cast<uint32_t*>(&h1));
}

// =================== HMMA fp16 x1 GEMM (base ISA) ===========================
// C[M,Ntot] = fp16(A)[M,512] @ fp16(B)[Ntot,512]^T (+bias), fp32 accum.
// Block 128x128, BK=64 (128B rows, XOR swizzle: chunk^=(row&7)), 4 warps
// (64x64 warp tiles), 128 threads, 3-stage cp.async with ONE sync per
// k-block (issue after barrier), 2 CTAs/SM.
#define AB_TILE_B 16384             // 128 rows * 128 bytes
#define NSTAGE   3
#define STAGE_TOT (2 * AB_TILE_B)   // 32768
#define GSMEM_BYTES (NSTAGE * STAGE_TOT)   // 98304 B

template <bool BIAS, typename OT>
__global__ __launch_bounds__(128, 2)
void gemm_mma_x1(const __half* __restrict__ Ah, const __half* __restrict__ Bh,
                 const float* __restrict__ bias, OT* __restrict__ C, int Ntot) {
    extern __shared__ __align__(128) char smem[];
    const uint32_t sb = smem_u32(smem);
    const int tid = threadIdx.x;
    const int wid = tid >> 5, lane = tid & 31;
    const int wm = wid & 1;          // 2 warps along M (64 rows each)
    const int wn = wid >> 1;         // 2 warps along N (64 cols each)
    const int bm = blockIdx.y * 128;
    const int bn = blockIdx.x * 128;

    const __half* srcA = Ah + (size_t)bm * 512;
    const __half* srcB = Bh + (size_t)bn * 512;

    // Per stage: A/B each 128 rows x 8 chunks(16B) = 1024 chunks; 8/thread.
#define ISSUE_STAGE(BUF, K0)                                                   \
    {                                                                          \
        uint32_t baseA = sb + (BUF) * STAGE_TOT;                               \
        uint32_t baseB = baseA + AB_TILE_B;                                    \
        _Pragma("unroll")                                                      \
        for (int i = 0; i < 8; i++) {                                          \
            int ch = i * 128 + tid;                                            \
            int r = ch >> 3, c = ch & 7;                                       \
            uint32_t pc = (uint32_t)(c ^ (r & 7)) << 4;                        \
            cp_async16(baseA + r * 128 + pc,                                   \
                       srcA + (size_t)r * 512 + (K0) + c * 8);                 \
            cp_async16(baseB + r * 128 + pc,                                   \
                       srcB + (size_t)r * 512 + (K0) + c * 8);                 \
        }                                                                      \
        cp_commit();                                                           \
    }

    float acc[4][8][4];
#pragma unroll
    for (int i = 0; i < 4; i++)
#pragma unroll
        for (int j = 0; j < 8; j++)
#pragma unroll
            for (int k = 0; k < 4; k++) acc[i][j][k] = 0.f;

    ISSUE_STAGE(0, 0)
    ISSUE_STAGE(1, 64)

    const uint32_t a_row = (lane & 15);
    const int a_cbase = (lane >> 4);           // chunk low bit for A
    const uint32_t b_row = (lane & 7) + ((lane >> 4) & 1) * 8;
    const int b_cbase = ((lane >> 3) & 1);     // chunk low bit for B

#pragma unroll 1
    for (int kb = 0; kb < 8; kb++) {
        if (kb < 7) cp_wait<1>(); else cp_wait<0>();
        __syncthreads();
        if (kb < 6) ISSUE_STAGE((kb + 2) % NSTAGE, (kb + 2) * 64);

        const uint32_t sA = sb + (kb % NSTAGE) * STAGE_TOT;
        const uint32_t sB = sA + AB_TILE_B;
#pragma unroll
        for (int ks = 0; ks < 4; ks++) {
            const int ca = ks * 2 + a_cbase;
            const int cb = ks * 2 + b_cbase;
            uint32_t aH[4][4], bH[4][4];
#pragma unroll
            for (int mt = 0; mt < 4; mt++) {
                uint32_t r = wm * 64 + mt * 16 + a_row;
                ldsm_x4(sA + r * 128 + ((uint32_t)(ca ^ (r & 7)) << 4), aH[mt]);
            }
#pragma unroll
            for (int nt2 = 0; nt2 < 4; nt2++) {
                uint32_t r = wn * 64 + nt2 * 16 + b_row;
                ldsm_x4(sB + r * 128 + ((uint32_t)(cb ^ (r & 7)) << 4), bH[nt2]);
            }
#pragma unroll
            for (int mt = 0; mt < 4; mt++)
#pragma unroll
                for (int nt2 = 0; nt2 < 4; nt2++) {
                    mma_16816(acc[mt][nt2 * 2 + 0], aH[mt], bH[nt2][0], bH[nt2][1]);
                    mma_16816(acc[mt][nt2 * 2 + 1], aH[mt], bH[nt2][2], bH[nt2][3]);
                }
        }
    }
#undef ISSUE_STAGE

#pragma unroll
    for (int mt = 0; mt < 4; mt++) {
        int row = bm + wm * 64 + mt * 16 + (lane >> 2);
#pragma unroll
        for (int nt = 0; nt < 8; nt++) {
            int col = bn + wn * 64 + nt * 8 + 2 * (lane & 3);
            float bx = 0.f, by = 0.f;
            if (BIAS) { bx = __ldg(bias + col); by = __ldg(bias + col + 1); }
            float v00 = acc[mt][nt][0] + bx, v01 = acc[mt][nt][1] + by;
            float v10 = acc[mt][nt][2] + bx, v11 = acc[mt][nt][3] + by;
            if constexpr (sizeof(OT) == 2) {
                *reinterpret_cast<__half2*>((__half*)C + (size_t)row * Ntot + col) =
                    __floats2half2_rn(v00, v01);
                *reinterpret_cast<__half2*>((__half*)C + (size_t)(row + 8) * Ntot + col) =
                    __floats2half2_rn(v10, v11);
            } else {
                *reinterpret_cast<float2*>((float*)C + (size_t)row * Ntot + col) =
                    make_float2(v00, v01);
                *reinterpret_cast<float2*>((float*)C + (size_t)(row + 8) * Ntot + col) =
                    make_float2(v10, v11);
            }
        }
    }
}

// =================== weight-vector prep =====================================
__global__ void make_wq(const float* __restrict__ wql, float* __restrict__ wvec) {
    int t = blockIdx.x * blockDim.x + threadIdx.x;
    if (t < BH * DHq) wvec[t] = wql[t & 63];
}
__global__ void make_wk(const float* __restrict__ wkl, const float* __restrict__ gq,
                        float* __restrict__ wvec) {
    int t = blockIdx.x * blockDim.x + threadIdx.x;
    if (t < BH * DHq) wvec[t] = wkl[t & 63] * gq[t];
}

// ============ fused softmax partial: logits + exp + weighted sums ===========
#define FPAD 72   // halfs per token in smem (144 B, 16B-aligned)

__global__ __launch_bounds__(256)
void fused_softmax_partial(const __half* __restrict__ qkv, int off,
                           const float* __restrict__ wvec,
                           const unsigned char* __restrict__ mask,
                           float* __restrict__ part) {
    __shared__ __align__(16) __half sq[256 * FPAD];
    __shared__ float swv[64];
    __shared__ float sw[256];
    __shared__ float red[256];
    __shared__ float sv[4][64];

    const int chunk = blockIdx.x, bh = blockIdx.y;
    const int b = bh >> 3, h = bh & 7;
    const int tid = threadIdx.x;
    const int row0 = b * Nq + h * 1024 + chunk * 32;

#pragma unroll
    for (int i = 0; i < 8; i++) {
        int ch = i * 256 + tid;
        int tl = ch >> 3, d8 = ch & 7;
        const __half* src = qkv + (size_t)(row0 + (tl >> 3)) * QKV_COLS
                            + off + (tl & 7) * 64 + d8 * 8;
        *reinterpret_cast<uint4*>(sq + tl * FPAD + d8 * 8) =
            *reinterpret_cast<const uint4*>(src);
    }
    if (tid < 64) swv[tid] = wvec[bh * 64 + tid];
    __syncthreads();

    float dot = 0.f;
    const __half* q = sq + tid * FPAD;
#pragma unroll
    for (int d = 0; d < 64; d += 2) {
        float2 qq = __half22float2(*reinterpret_cast<const __half2*>(q + d));
        dot += qq.x * swv[d] + qq.y * swv[d + 1];
    }
    float w = __expf(dot * SCALEq);
    if (mask[b * Nq + chunk * 256 + tid]) w = 0.f;
    sw[tid] = w;
    red[tid] = w;
    __syncthreads();
    for (int s = 128; s > 0; s >>= 1) {
        if (tid < s) red[tid] += red[tid + s];
        __syncthreads();
    }

    const int d = tid & 63, g = tid >> 6;
    float acc = 0.f;
#pragma unroll 8
    for (int tl = g * 64; tl < g * 64 + 64; tl++)
        acc += sw[tl] * __half2float(sq[tl * FPAD + d]);
    sv[g][d] = acc;
    __syncthreads();
    if (tid < 64) {
        float* rec = part + (size_t)(bh * CHUNKS + chunk) * REC;
        rec[tid] = sv[0][tid] + sv[1][tid] + sv[2][tid] + sv[3][tid];
        if (tid == 0) rec[64] = red[0];
    }
}

__global__ void finalize_reduce(const float* __restrict__ part,
                                float* __restrict__ gout) {
    int bh = blockIdx.x;
    int d = threadIdx.x;
    const float* base = part + (size_t)bh * CHUNKS * REC;
    float v = 0.f, w = 0.f;
#pragma unroll
    for (int c = 0; c < CHUNKS; c++) {
        v += base[c * REC + d];
        w += base[c * REC + 64];
    }
    gout[bh * 64 + d] = v / w;
}

// ============ compute_r via HMMA: R = A'[256x64] @ Mw^T + q + b_r ===========
#define CR_ROWS 32
#define CR_PAD  72

__global__ __launch_bounds__(256)
void compute_r_mma(const __half* __restrict__ qkv,
                   const float* __restrict__ gk,
                   const float* __restrict__ W_r,
                   const float* __restrict__ b_r,
                   __half* __restrict__ Rh) {
    __shared__ __align__(16) __half sA[256 * CR_PAD];
    __shared__ __align__(16) __half sB[64 * CR_PAD];
    __shared__ float sbr[64];

    const int tid = threadIdx.x;
    const int wid = tid >> 5, lane = tid & 31;
    const int row0 = blockIdx.x * CR_ROWS;
    const int bh = (row0 >> 13) * 8 + ((row0 & (Nq - 1)) >> 10);

#pragma unroll
    for (int i = 0; i < 8; i++) {
        int ch = i * 256 + tid;
        int tok = ch >> 3, d8 = ch & 7;
        const __half* src = qkv + (size_t)(row0 + (tok >> 3)) * QKV_COLS
                            + 1024 + (tok & 7) * 64 + d8 * 8;
        *reinterpret_cast<uint4*>(sA + tok * CR_PAD + d8 * 8) =
            *reinterpret_cast<const uint4*>(src);
    }

    {
        int e = tid >> 2, db = (tid & 3) * 16;
        const float* wr = W_r + e * 64 + db;
        const float* gkp = gk + bh * 64 + db;
        __half tmp[16];
#pragma unroll
        for (int j = 0; j < 16; j += 4) {
            float4 w4 = *reinterpret_cast<const float4*>(wr + j);
            float4 g4 = *reinterpret_cast<const float4*>(gkp + j);
            tmp[j + 0] = __float2half_rn(w4.x * g4.x);
            tmp[j + 1] = __float2half_rn(w4.y * g4.y);
            tmp[j + 2] = __float2half_rn(w4.z * g4.z);
            tmp[j + 3] = __float2half_rn(w4.w * g4.w);
        }
        *reinterpret_cast<uint4*>(sB + e * CR_PAD + db) =
            *reinterpret_cast<uint4*>(tmp);
        *reinterpret_cast<uint4*>(sB + e * CR_PAD + db + 8) =
            *reinterpret_cast<uint4*>(tmp + 8);
    }
    if (tid < 64) sbr[tid] = b_r[tid];
    __syncthreads();

    const uint32_t sAu = smem_u32(sA);
    const uint32_t sBu = smem_u32(sB);
    const uint32_t a_row = (lane & 15);
    const uint32_t a_half = (lane >> 4) * 16;
    const uint32_t b_row = (lane & 7) + ((lane >> 4) & 1) * 8;
    const uint32_t b_half = ((lane >> 3) & 1) * 16;

    float c[2][8][4];
#pragma unroll
    for (int i = 0; i < 2; i++)
#pragma unroll
        for (int j = 0; j < 8; j++)
#pragma unroll
            for (int k = 0; k < 4; k++) c[i][j][k] = 0.f;

#pragma unroll
    for (int k = 0; k < 4; k++) {
        uint32_t aH[2][4], bH[4][4];
#pragma unroll
        for (int mt = 0; mt < 2; mt++)
            ldsm_x4(sAu + (wid * 32 + mt * 16 + a_row) * 144 + a_half + k * 32,
                    aH[mt]);
#pragma unroll
        for (int nt2 = 0; nt2 < 4; nt2++)
            ldsm_x4(sBu + (nt2 * 16 + b_row) * 144 + b_half + k * 32, bH[nt2]);
#pragma unroll
        for (int mt = 0; mt < 2; mt++)
#pragma unroll
            for (int nt2 = 0; nt2 < 4; nt2++) {
                mma_16816(c[mt][nt2 * 2 + 0], aH[mt], bH[nt2][0], bH[nt2][1]);
                mma_16816(c[mt][nt2 * 2 + 1], aH[mt], bH[nt2][2], bH[nt2][3]);
            }
    }

#pragma unroll
    for (int mt = 0; mt < 2; mt++) {
        int t0 = wid * 32 + mt * 16 + (lane >> 2);
#pragma unroll
        for (int nt = 0; nt < 8; nt++) {
            int e = nt * 8 + 2 * (lane & 3);
            float br0 = sbr[e], br1 = sbr[e + 1];
#pragma unroll
            for (int half = 0; half < 2; half++) {
                int t = t0 + half * 8;
                size_t base = (size_t)(row0 + (t >> 3));
                int col = (t & 7) * 64 + e;
                float2 q = __half22float2(*reinterpret_cast<const __half2*>(
                    qkv + base * QKV_COLS + col));
                float o0 = c[mt][nt][half * 2 + 0] + q.x + br0;
                float o1 = c[mt][nt][half * 2 + 1] + q.y + br1;
                __half2 hv = __floats2half2_rn(o0, o1);
                *reinterpret_cast<__half2*>(Rh + base * INNERq + col) = hv;
            }
        }
    }
}

// ---------------- launcher --------------------------------------------------
extern "C" void kernel_launch(void* const* d_in, const int* in_sizes, int n_in,
                              void* d_out, int out_size) {
    const float* x     = (const float*)d_in[0];
    const unsigned char* mask = (const unsigned char*)d_in[1];
    const float* W_qkv = (const float*)d_in[2];
    const float* w_q   = (const float*)d_in[3];
    const float* w_k   = (const float*)d_in[4];
    const float* W_r   = (const float*)d_in[5];
    const float* b_r   = (const float*)d_in[6];
    const float* W_out = (const float*)d_in[7];
    const float* b_out = (const float*)d_in[8];
    float* out = (float*)d_out;

    float *gq, *gk, *wvec, *part;
    __half *qkv, *xh, *Rh, *Wqh, *Woh;
    cudaGetSymbolAddress((void**)&qkv,  g_qkv);
    cudaGetSymbolAddress((void**)&gq,   g_gq);
    cudaGetSymbolAddress((void**)&gk,   g_gk);
    cudaGetSymbolAddress((void**)&wvec, g_wvec);
    cudaGetSymbolAddress((void**)&part, g_part);
    cudaGetSymbolAddress((void**)&xh,   g_xh);
    cudaGetSymbolAddress((void**)&Rh,   g_Rh);
    cudaGetSymbolAddress((void**)&Wqh,  g_Wqh);
    cudaGetSymbolAddress((void**)&Woh,  g_Woh);

    static int smem_set = 0;
    if (!smem_set) {
        cudaFuncSetAttribute((const void*)gemm_mma_x1<false, __half>,
                             cudaFuncAttributeMaxDynamicSharedMemorySize, GSMEM_BYTES);
        cudaFuncSetAttribute((const void*)gemm_mma_x1<true, float>,
                             cudaFuncAttributeMaxDynamicSharedMemorySize, GSMEM_BYTES);
        smem_set = 1;
    }

    // 0) conversions: x -> fp16; weights -> fp16
    convert_h_kernel<<<(M_TOTAL * DIMq) / 1024, 256>>>(x, xh);
    convert_h_kernel<<<(QKV_COLS * DIMq) / 1024, 256>>>(W_qkv, Wqh);
    convert_h_kernel<<<(DIMq * INNERq) / 1024, 256>>>(W_out, Woh);

    // 1) qkv = x @ W_qkv^T  (HMMA fp16 x1, BK=64 single-sync, fp16 output)
    gemm_mma_x1<false, __half><<<dim3(QKV_COLS / 128, M_TOTAL / 128), 128,
                                 GSMEM_BYTES>>>(xh, Wqh, nullptr, qkv, QKV_COLS);

    // 2) q softmax -> global_q  (fused logits+exp+partial)
    make_wq<<<(BH * DHq + 255) / 256, 256>>>(w_q, wvec);
    fused_softmax_partial<<<dim3(CHUNKS, BH), 256>>>(qkv, 0, wvec, mask, part);
    finalize_reduce<<<BH, 64>>>(part, gq);

    // 3) k softmax -> global_k
    make_wk<<<(BH * DHq + 255) / 256, 256>>>(w_k, gq, wvec);
    fused_softmax_partial<<<dim3(CHUNKS, BH), 256>>>(qkv, DIMq, wvec, mask, part);
    finalize_reduce<<<BH, 64>>>(part, gk);

    // 4) r = (v*gk) @ W_r^T + b_r + q  (HMMA, fp16 in/out)
    compute_r_mma<<<M_TOTAL / CR_ROWS, 256>>>(qkv, gk, W_r, b_r, Rh);

    // 5) out = r @ W_out^T + b_out  (HMMA fp16 x1, fp32 output)
    gemm_mma_x1<true, float><<<dim3(INNERq / 128, M_TOTAL / 128), 128,
                               GSMEM_BYTES>>>(Rh, Woh, b_out, out, INNERq);
}